// round 1
// baseline (speedup 1.0000x reference)
#include <cuda_runtime.h>
#include <math.h>

#define BATCH_MAX 65536
#define FEAT 584

// Scratch (allocation-free rule: __device__ globals)
__device__ float g_feats[(size_t)BATCH_MAX * FEAT];   // conv features + quantum
__device__ float g_c1[(size_t)BATCH_MAX * 192];       // relu(feats @ [pt_w1|cf_w1] + b)

// ---------------------------------------------------------------------------
// Kernel 1: conv pipeline + quantum sim -> g_feats
// One warp per sample, 4 warps / 128-thread block. Zero-padded smem layouts
// make SAME-padding branch-free.
// Per-warp smem regions (floats):
//   [0..192)     in_p  3x8x8 padded board
//   [192..1216)  h1_p 16x8x8 padded conv1 out   (later aliased by pooled 32x5x5 = 800)
//   [1216..2368) h2   32x36 conv2 out (unpadded)
// ---------------------------------------------------------------------------
__global__ __launch_bounds__(128) void k_conv(
    const float* __restrict__ board,
    const float* __restrict__ w1, const float* __restrict__ b1,
    const float* __restrict__ w2, const float* __restrict__ b2,
    const float* __restrict__ w3, const float* __restrict__ b3,
    const float* __restrict__ qp, int nsamp)
{
    __shared__ float sm[4][2368];
    const int warp = threadIdx.x >> 5;
    const int lane = threadIdx.x & 31;
    const int s = blockIdx.x * 4 + warp;
    if (s >= nsamp) return;

    float* inp = sm[warp];          // 192
    float* h1p = sm[warp] + 192;    // 1024 ; later pooled-padded (800)
    float* h2  = sm[warp] + 1216;   // 1152
    float* pp  = h1p;               // alias (h1p dead before pooling)

    const float* bs = board + (size_t)s * 108;

    // ---- zero padded buffers
    #pragma unroll
    for (int i = lane; i < 192; i += 32)  inp[i] = 0.f;
    #pragma unroll
    for (int i = lane; i < 1024; i += 32) h1p[i] = 0.f;
    __syncwarp();

    // ---- load board into padded interior
    for (int i = lane; i < 108; i += 32) {
        int ci = i / 36, r = i - ci * 36;
        int y = r / 6, x = r - y * 6;
        inp[ci * 64 + (y + 1) * 8 + (x + 1)] = bs[i];
    }

    // ---- quantum sim (lanes 0..7), independent of convs
    if (lane < 8) {
        float xv = bs[lane];
        float xn = bs[(lane + 1) & 7];
        float q = 0.f;
        #pragma unroll
        for (int l = 0; l < 3; l++) {
            float r0 = __ldg(qp + (l * 8 + lane) * 3 + 0);
            float r1 = __ldg(qp + (l * 8 + lane) * 3 + 1);
            float r2 = __ldg(qp + (l * 8 + lane) * 3 + 2);
            q = sinf(r0 * xv) * cosf(r1 * xn) + tanhf(r2 * q);
        }
        g_feats[(size_t)s * FEAT + 576 + lane] = q;
    }
    __syncwarp();

    // ---- conv1: 3->16, 6x6 SAME, relu.  lane&15 = c_out, lane>>4 = pixel half
    {
        const int co = lane & 15, half = lane >> 4;
        float w[27];
        #pragma unroll
        for (int i = 0; i < 27; i++) w[i] = __ldg(w1 + co * 27 + i);
        const float bias = __ldg(b1 + co);
        #pragma unroll
        for (int p = 0; p < 18; p++) {
            const int y8 = (half * 3 + p / 6) * 8;  // padded row base for output y
            const int xx = p % 6;
            float a = bias;
            #pragma unroll
            for (int ci = 0; ci < 3; ci++)
                #pragma unroll
                for (int ky = 0; ky < 3; ky++)
                    #pragma unroll
                    for (int kx = 0; kx < 3; kx++)
                        a = fmaf(inp[ci * 64 + y8 + ky * 8 + xx + kx],
                                 w[ci * 9 + ky * 3 + kx], a);
            h1p[co * 64 + y8 + 8 + xx + 1] = fmaxf(a, 0.f);
        }
    }
    __syncwarp();

    // ---- conv2: 16->32, 6x6 SAME, relu.  lane = c_out
    {
        const int co = lane;
        float acc[36];
        const float bias = __ldg(b2 + co);
        #pragma unroll
        for (int i = 0; i < 36; i++) acc[i] = bias;

        for (int ci = 0; ci < 16; ci++) {
            const float* hr = h1p + ci * 64;
            const float* wp = w2 + (co * 16 + ci) * 9;
            float w[9];
            #pragma unroll
            for (int i = 0; i < 9; i++) w[i] = __ldg(wp + i);
            float rows[3][8];
            #pragma unroll
            for (int x = 0; x < 8; x++) { rows[0][x] = hr[x]; rows[1][x] = hr[8 + x]; }
            #pragma unroll
            for (int y = 0; y < 6; y++) {
                #pragma unroll
                for (int x = 0; x < 8; x++) rows[(y + 2) % 3][x] = hr[(y + 2) * 8 + x];
                #pragma unroll
                for (int x = 0; x < 6; x++) {
                    float a = acc[y * 6 + x];
                    a = fmaf(rows[(y + 0) % 3][x + 0], w[0], a);
                    a = fmaf(rows[(y + 0) % 3][x + 1], w[1], a);
                    a = fmaf(rows[(y + 0) % 3][x + 2], w[2], a);
                    a = fmaf(rows[(y + 1) % 3][x + 0], w[3], a);
                    a = fmaf(rows[(y + 1) % 3][x + 1], w[4], a);
                    a = fmaf(rows[(y + 1) % 3][x + 2], w[5], a);
                    a = fmaf(rows[(y + 2) % 3][x + 0], w[6], a);
                    a = fmaf(rows[(y + 2) % 3][x + 1], w[7], a);
                    a = fmaf(rows[(y + 2) % 3][x + 2], w[8], a);
                    acc[y * 6 + x] = a;
                }
            }
        }
        #pragma unroll
        for (int i = 0; i < 36; i++) h2[co * 36 + i] = fmaxf(acc[i], 0.f);
    }
    __syncwarp();

    // ---- maxpool 2x2 -> padded 32x5x5 (in pp, aliasing dead h1p)
    #pragma unroll
    for (int i = lane; i < 800; i += 32) pp[i] = 0.f;
    __syncwarp();
    {
        const int c = lane;
        #pragma unroll
        for (int p = 0; p < 9; p++) {
            const int py = p / 3, px = p % 3;
            const float* b = h2 + c * 36 + (2 * py) * 6 + 2 * px;
            float m = fmaxf(fmaxf(b[0], b[1]), fmaxf(b[6], b[7]));
            pp[c * 25 + (py + 1) * 5 + (px + 1)] = m;
        }
    }
    __syncwarp();

    // ---- conv3: 32->64, 3x3 SAME, relu.  lane handles c_out = lane and lane+32
    {
        float acc0[9], acc1[9];
        const float bz0 = __ldg(b3 + lane), bz1 = __ldg(b3 + lane + 32);
        #pragma unroll
        for (int i = 0; i < 9; i++) { acc0[i] = bz0; acc1[i] = bz1; }

        for (int ci = 0; ci < 32; ci++) {
            float p[25];
            const float* ps = pp + ci * 25;
            #pragma unroll
            for (int i = 0; i < 25; i++) p[i] = ps[i];
            float wa[9], wb[9];
            const float* wpa = w3 + ((size_t)lane * 32 + ci) * 9;
            const float* wpb = w3 + ((size_t)(lane + 32) * 32 + ci) * 9;
            #pragma unroll
            for (int i = 0; i < 9; i++) { wa[i] = __ldg(wpa + i); wb[i] = __ldg(wpb + i); }
            #pragma unroll
            for (int y = 0; y < 3; y++)
                #pragma unroll
                for (int x = 0; x < 3; x++) {
                    float a0 = acc0[y * 3 + x], a1 = acc1[y * 3 + x];
                    #pragma unroll
                    for (int ky = 0; ky < 3; ky++)
                        #pragma unroll
                        for (int kx = 0; kx < 3; kx++) {
                            const float v = p[(y + ky) * 5 + x + kx];
                            a0 = fmaf(v, wa[ky * 3 + kx], a0);
                            a1 = fmaf(v, wb[ky * 3 + kx], a1);
                        }
                    acc0[y * 3 + x] = a0; acc1[y * 3 + x] = a1;
                }
        }
        float* f = g_feats + (size_t)s * FEAT;
        #pragma unroll
        for (int i = 0; i < 9; i++) {
            f[lane * 9 + i]        = fmaxf(acc0[i], 0.f);
            f[(lane + 32) * 9 + i] = fmaxf(acc1[i], 0.f);
        }
    }
}

// ---------------------------------------------------------------------------
// Kernel 2: C1 = relu(feats @ [pt_w1 | cf_w1] + [pt_b1 | cf_b1])
// Tiled fp32 GEMM: M=B, K=584, N=192. BM=64, BN=192, BK=8, 256 threads,
// thread tile 4x12.
// ---------------------------------------------------------------------------
__global__ __launch_bounds__(256) void k_fc1(
    const float* __restrict__ ptw1, const float* __restrict__ ptb1,
    const float* __restrict__ cfw1, const float* __restrict__ cfb1)
{
    __shared__ float As[8 * 68];    // [k][m], pad 68 to spread banks
    __shared__ float Bs[8 * 196];   // [k][n], pad 196

    const int t  = threadIdx.x;
    const int tx = t & 15, ty = t >> 4;
    const int m0 = blockIdx.x * 64;
    const int ka = t & 7, ma = t >> 3;

    float acc[4][12];
    #pragma unroll
    for (int r = 0; r < 4; r++)
        #pragma unroll
        for (int c = 0; c < 12; c++) acc[r][c] = 0.f;

    for (int k0 = 0; k0 < 584; k0 += 8) {
        As[ka * 68 + ma]      = g_feats[(size_t)(m0 + ma) * FEAT + k0 + ka];
        As[ka * 68 + ma + 32] = g_feats[(size_t)(m0 + ma + 32) * FEAT + k0 + ka];
        #pragma unroll
        for (int i = 0; i < 4; i++) {
            int idx = t + i * 256; int kk = idx >> 7, col = idx & 127;
            Bs[kk * 196 + col] = __ldg(ptw1 + (size_t)(k0 + kk) * 128 + col);
        }
        #pragma unroll
        for (int i = 0; i < 2; i++) {
            int idx = t + i * 256; int kk = idx >> 6, col = idx & 63;
            Bs[kk * 196 + 128 + col] = __ldg(cfw1 + (size_t)(k0 + kk) * 64 + col);
        }
        __syncthreads();
        #pragma unroll
        for (int kk = 0; kk < 8; kk++) {
            float4 a4 = *(const float4*)&As[kk * 68 + ty * 4];
            float4 b0 = *(const float4*)&Bs[kk * 196 + tx * 12];
            float4 b1 = *(const float4*)&Bs[kk * 196 + tx * 12 + 4];
            float4 b2 = *(const float4*)&Bs[kk * 196 + tx * 12 + 8];
            const float av[4]  = {a4.x, a4.y, a4.z, a4.w};
            const float bv[12] = {b0.x, b0.y, b0.z, b0.w,
                                  b1.x, b1.y, b1.z, b1.w,
                                  b2.x, b2.y, b2.z, b2.w};
            #pragma unroll
            for (int r = 0; r < 4; r++)
                #pragma unroll
                for (int c = 0; c < 12; c++)
                    acc[r][c] = fmaf(av[r], bv[c], acc[r][c]);
        }
        __syncthreads();
    }

    #pragma unroll
    for (int c = 0; c < 12; c++) {
        const int j = tx * 12 + c;
        const float bias = (j < 128) ? __ldg(ptb1 + j) : __ldg(cfb1 + j - 128);
        #pragma unroll
        for (int r = 0; r < 4; r++) {
            float v = fmaxf(acc[r][c] + bias, 0.f);
            g_c1[(size_t)(m0 + ty * 4 + r) * 192 + j] = v;
        }
    }
}

// ---------------------------------------------------------------------------
// Kernel 3: second-stage heads. One warp per sample.
// t2 = relu(C1[:, :128] @ pt_w2 + pt_b2); logits = t2 @ pt_w3 + pt_b3; softmax
// conf = sigmoid(C1[:, 128:] @ cf_w2 + cf_b2)
// ---------------------------------------------------------------------------
__global__ __launch_bounds__(256) void k_fc2(
    const float* __restrict__ ptw2, const float* __restrict__ ptb2,
    const float* __restrict__ ptw3, const float* __restrict__ ptb3,
    const float* __restrict__ cfw2, const float* __restrict__ cfb2,
    float* __restrict__ out, int nsamp)
{
    const int warp = threadIdx.x >> 5, lane = threadIdx.x & 31;
    const int m = blockIdx.x * 8 + warp;
    if (m >= nsamp) return;
    const float* c1 = g_c1 + (size_t)m * 192;

    float a0 = __ldg(ptb2 + lane), a1 = __ldg(ptb2 + lane + 32);
    #pragma unroll 8
    for (int k4 = 0; k4 < 32; k4++) {
        const float4 h = __ldg((const float4*)(c1 + k4 * 4));
        const int k = k4 * 4;
        a0 = fmaf(h.x, __ldg(ptw2 + (k + 0) * 64 + lane), a0);
        a1 = fmaf(h.x, __ldg(ptw2 + (k + 0) * 64 + lane + 32), a1);
        a0 = fmaf(h.y, __ldg(ptw2 + (k + 1) * 64 + lane), a0);
        a1 = fmaf(h.y, __ldg(ptw2 + (k + 1) * 64 + lane + 32), a1);
        a0 = fmaf(h.z, __ldg(ptw2 + (k + 2) * 64 + lane), a0);
        a1 = fmaf(h.z, __ldg(ptw2 + (k + 2) * 64 + lane + 32), a1);
        a0 = fmaf(h.w, __ldg(ptw2 + (k + 3) * 64 + lane), a0);
        a1 = fmaf(h.w, __ldg(ptw2 + (k + 3) * 64 + lane + 32), a1);
    }
    a0 = fmaxf(a0, 0.f); a1 = fmaxf(a1, 0.f);

    float l0 = a0 * __ldg(ptw3 + lane * 2)     + a1 * __ldg(ptw3 + (lane + 32) * 2);
    float l1 = a0 * __ldg(ptw3 + lane * 2 + 1) + a1 * __ldg(ptw3 + (lane + 32) * 2 + 1);
    const float hc0 = c1[128 + lane], hc1 = c1[160 + lane];
    float cc = hc0 * __ldg(cfw2 + lane) + hc1 * __ldg(cfw2 + lane + 32);

    #pragma unroll
    for (int off = 16; off; off >>= 1) {
        l0 += __shfl_xor_sync(0xffffffffu, l0, off);
        l1 += __shfl_xor_sync(0xffffffffu, l1, off);
        cc += __shfl_xor_sync(0xffffffffu, cc, off);
    }
    if (lane == 0) {
        l0 += __ldg(ptb3 + 0); l1 += __ldg(ptb3 + 1);
        const float mx = fmaxf(l0, l1);
        const float e0 = expf(l0 - mx), e1 = expf(l1 - mx);
        const float inv = 1.f / (e0 + e1);
        const float conf = 1.f / (1.f + expf(-(cc + __ldg(cfb2))));
        out[(size_t)m * 3 + 0] = e0 * inv;
        out[(size_t)m * 3 + 1] = e1 * inv;
        out[(size_t)m * 3 + 2] = conf;
    }
}

// ---------------------------------------------------------------------------
extern "C" void kernel_launch(void* const* d_in, const int* in_sizes, int n_in,
                              void* d_out, int out_size)
{
    const float* board = (const float*)d_in[0];
    // d_in[1] = target_positions (int64) — mathematically unused
    const float* c1w = (const float*)d_in[2];  const float* c1b = (const float*)d_in[3];
    const float* c2w = (const float*)d_in[4];  const float* c2b = (const float*)d_in[5];
    const float* c3w = (const float*)d_in[6];  const float* c3b = (const float*)d_in[7];
    const float* qp  = (const float*)d_in[8];
    const float* ptw1 = (const float*)d_in[9];  const float* ptb1 = (const float*)d_in[10];
    const float* ptw2 = (const float*)d_in[11]; const float* ptb2 = (const float*)d_in[12];
    const float* ptw3 = (const float*)d_in[13]; const float* ptb3 = (const float*)d_in[14];
    const float* cfw1 = (const float*)d_in[15]; const float* cfb1 = (const float*)d_in[16];
    const float* cfw2 = (const float*)d_in[17]; const float* cfb2 = (const float*)d_in[18];

    int B = in_sizes[0] / 108;
    if (B > BATCH_MAX) B = BATCH_MAX;

    k_conv<<<(B + 3) / 4, 128>>>(board, c1w, c1b, c2w, c2b, c3w, c3b, qp, B);
    k_fc1<<<B / 64, 256>>>(ptw1, ptb1, cfw1, cfb1);
    k_fc2<<<(B + 7) / 8, 256>>>(ptw2, ptb2, ptw3, ptb3, cfw2, cfb2, (float*)d_out, B);
}

// round 2
// speedup vs baseline: 3.7711x; 3.7711x over previous
#include <cuda_runtime.h>
#include <math.h>

#define BATCH_MAX 65536
#define FEAT 584

// Scratch (allocation-free rule: __device__ globals)
__device__ float g_feats[(size_t)BATCH_MAX * FEAT];   // conv features + quantum
__device__ float g_c1[(size_t)BATCH_MAX * 192];       // relu(feats @ [pt_w1|cf_w1] + b)

// Transposed weight copies (lane-coalesced layouts)
__device__ float g_w1t[27 * 16];     // [tap][co]
__device__ float g_w2t[144 * 32];    // [ci*9+tap][co]
__device__ float g_w3t[288 * 64];    // [ci*9+tap][co]

// ---------------------------------------------------------------------------
// Kernel 0: transpose conv weights into lane-coalesced layouts.
// w1 (16,3,3,3): g_w1t[t*16+co]   = w1[co*27+t]
// w2 (32,16,3,3): g_w2t[r*32+co]  = w2[co*144+r]   (r = ci*9+tap)
// w3 (64,32,3,3): g_w3t[r*64+co]  = w3[co*288+r]
// ---------------------------------------------------------------------------
__global__ void k_wt(const float* __restrict__ w1,
                     const float* __restrict__ w2,
                     const float* __restrict__ w3)
{
    const int i = blockIdx.x * 256 + threadIdx.x;
    if (i < 432)   { int co = i / 27,  r = i - co * 27;  g_w1t[r * 16 + co] = w1[i]; }
    if (i < 4608)  { int co = i / 144, r = i - co * 144; g_w2t[r * 32 + co] = w2[i]; }
    if (i < 18432) { int co = i / 288, r = i - co * 288; g_w3t[r * 64 + co] = w3[i]; }
}

// ---------------------------------------------------------------------------
// Kernel 1: conv pipeline + quantum sim -> g_feats
// One warp per sample, 4 warps / 128-thread block. Zero-padded smem layouts
// make SAME-padding branch-free. All weight loads are lane-coalesced via the
// transposed copies (1 L1 wavefront per LDG instead of 32).
// ---------------------------------------------------------------------------
__global__ __launch_bounds__(128) void k_conv(
    const float* __restrict__ board,
    const float* __restrict__ b1,
    const float* __restrict__ b2,
    const float* __restrict__ b3,
    const float* __restrict__ qp, int nsamp)
{
    __shared__ float sm[4][2368];
    const int warp = threadIdx.x >> 5;
    const int lane = threadIdx.x & 31;
    const int s = blockIdx.x * 4 + warp;
    if (s >= nsamp) return;

    float* inp = sm[warp];          // 192
    float* h1p = sm[warp] + 192;    // 1024 ; later pooled-padded (800)
    float* h2  = sm[warp] + 1216;   // 1152
    float* pp  = h1p;               // alias (h1p dead before pooling)

    const float* bs = board + (size_t)s * 108;

    // ---- zero padded buffers
    #pragma unroll
    for (int i = lane; i < 192; i += 32)  inp[i] = 0.f;
    #pragma unroll
    for (int i = lane; i < 1024; i += 32) h1p[i] = 0.f;
    __syncwarp();

    // ---- load board into padded interior
    for (int i = lane; i < 108; i += 32) {
        int ci = i / 36, r = i - ci * 36;
        int y = r / 6, x = r - y * 6;
        inp[ci * 64 + (y + 1) * 8 + (x + 1)] = bs[i];
    }

    // ---- quantum sim (lanes 0..7), independent of convs
    if (lane < 8) {
        float xv = bs[lane];
        float xn = bs[(lane + 1) & 7];
        float q = 0.f;
        #pragma unroll
        for (int l = 0; l < 3; l++) {
            float r0 = __ldg(qp + (l * 8 + lane) * 3 + 0);
            float r1 = __ldg(qp + (l * 8 + lane) * 3 + 1);
            float r2 = __ldg(qp + (l * 8 + lane) * 3 + 2);
            q = sinf(r0 * xv) * cosf(r1 * xn) + tanhf(r2 * q);
        }
        g_feats[(size_t)s * FEAT + 576 + lane] = q;
    }
    __syncwarp();

    // ---- conv1: 3->16, 6x6 SAME, relu.  lane&15 = c_out, lane>>4 = pixel half
    {
        const int co = lane & 15, half = lane >> 4;
        float w[27];
        #pragma unroll
        for (int i = 0; i < 27; i++) w[i] = __ldg(g_w1t + i * 16 + co);
        const float bias = __ldg(b1 + co);
        #pragma unroll
        for (int p = 0; p < 18; p++) {
            const int y8 = (half * 3 + p / 6) * 8;  // padded row base for output y
            const int xx = p % 6;
            float a = bias;
            #pragma unroll
            for (int ci = 0; ci < 3; ci++)
                #pragma unroll
                for (int ky = 0; ky < 3; ky++)
                    #pragma unroll
                    for (int kx = 0; kx < 3; kx++)
                        a = fmaf(inp[ci * 64 + y8 + ky * 8 + xx + kx],
                                 w[ci * 9 + ky * 3 + kx], a);
            h1p[co * 64 + y8 + 8 + xx + 1] = fmaxf(a, 0.f);
        }
    }
    __syncwarp();

    // ---- conv2: 16->32, 6x6 SAME, relu.  lane = c_out
    {
        float acc[36];
        const float bias = __ldg(b2 + lane);
        #pragma unroll
        for (int i = 0; i < 36; i++) acc[i] = bias;

        for (int ci = 0; ci < 16; ci++) {
            const float* hr = h1p + ci * 64;
            float w[9];
            #pragma unroll
            for (int i = 0; i < 9; i++) w[i] = __ldg(g_w2t + (ci * 9 + i) * 32 + lane);
            float rows[3][8];
            #pragma unroll
            for (int x = 0; x < 8; x++) { rows[0][x] = hr[x]; rows[1][x] = hr[8 + x]; }
            #pragma unroll
            for (int y = 0; y < 6; y++) {
                #pragma unroll
                for (int x = 0; x < 8; x++) rows[(y + 2) % 3][x] = hr[(y + 2) * 8 + x];
                #pragma unroll
                for (int x = 0; x < 6; x++) {
                    float a = acc[y * 6 + x];
                    a = fmaf(rows[(y + 0) % 3][x + 0], w[0], a);
                    a = fmaf(rows[(y + 0) % 3][x + 1], w[1], a);
                    a = fmaf(rows[(y + 0) % 3][x + 2], w[2], a);
                    a = fmaf(rows[(y + 1) % 3][x + 0], w[3], a);
                    a = fmaf(rows[(y + 1) % 3][x + 1], w[4], a);
                    a = fmaf(rows[(y + 1) % 3][x + 2], w[5], a);
                    a = fmaf(rows[(y + 2) % 3][x + 0], w[6], a);
                    a = fmaf(rows[(y + 2) % 3][x + 1], w[7], a);
                    a = fmaf(rows[(y + 2) % 3][x + 2], w[8], a);
                    acc[y * 6 + x] = a;
                }
            }
        }
        #pragma unroll
        for (int i = 0; i < 36; i++) h2[lane * 36 + i] = fmaxf(acc[i], 0.f);
    }
    __syncwarp();

    // ---- maxpool 2x2 -> padded 32x5x5 (in pp, aliasing dead h1p)
    #pragma unroll
    for (int i = lane; i < 800; i += 32) pp[i] = 0.f;
    __syncwarp();
    {
        const int c = lane;
        #pragma unroll
        for (int p = 0; p < 9; p++) {
            const int py = p / 3, px = p % 3;
            const float* b = h2 + c * 36 + (2 * py) * 6 + 2 * px;
            float m = fmaxf(fmaxf(b[0], b[1]), fmaxf(b[6], b[7]));
            pp[c * 25 + (py + 1) * 5 + (px + 1)] = m;
        }
    }
    __syncwarp();

    // ---- conv3: 32->64, 3x3 SAME, relu.  lane handles c_out = lane and lane+32
    {
        float acc0[9], acc1[9];
        const float bz0 = __ldg(b3 + lane), bz1 = __ldg(b3 + lane + 32);
        #pragma unroll
        for (int i = 0; i < 9; i++) { acc0[i] = bz0; acc1[i] = bz1; }

        for (int ci = 0; ci < 32; ci++) {
            float p[25];
            const float* ps = pp + ci * 25;
            #pragma unroll
            for (int i = 0; i < 25; i++) p[i] = ps[i];
            float wa[9], wb[9];
            #pragma unroll
            for (int i = 0; i < 9; i++) {
                wa[i] = __ldg(g_w3t + (ci * 9 + i) * 64 + lane);
                wb[i] = __ldg(g_w3t + (ci * 9 + i) * 64 + lane + 32);
            }
            #pragma unroll
            for (int y = 0; y < 3; y++)
                #pragma unroll
                for (int x = 0; x < 3; x++) {
                    float a0 = acc0[y * 3 + x], a1 = acc1[y * 3 + x];
                    #pragma unroll
                    for (int ky = 0; ky < 3; ky++)
                        #pragma unroll
                        for (int kx = 0; kx < 3; kx++) {
                            const float v = p[(y + ky) * 5 + x + kx];
                            a0 = fmaf(v, wa[ky * 3 + kx], a0);
                            a1 = fmaf(v, wb[ky * 3 + kx], a1);
                        }
                    acc0[y * 3 + x] = a0; acc1[y * 3 + x] = a1;
                }
        }
        float* f = g_feats + (size_t)s * FEAT;
        #pragma unroll
        for (int i = 0; i < 9; i++) {
            f[lane * 9 + i]        = fmaxf(acc0[i], 0.f);
            f[(lane + 32) * 9 + i] = fmaxf(acc1[i], 0.f);
        }
    }
}

// ---------------------------------------------------------------------------
// Kernel 2: C1 = relu(feats @ [pt_w1 | cf_w1] + [pt_b1 | cf_b1])
// Tiled fp32 GEMM: M=B, K=584, N=192. BM=64, BN=192, BK=8, 256 threads,
// thread tile 4x12.
// ---------------------------------------------------------------------------
__global__ __launch_bounds__(256) void k_fc1(
    const float* __restrict__ ptw1, const float* __restrict__ ptb1,
    const float* __restrict__ cfw1, const float* __restrict__ cfb1)
{
    __shared__ float As[8 * 68];    // [k][m], pad 68 to spread banks
    __shared__ float Bs[8 * 196];   // [k][n], pad 196

    const int t  = threadIdx.x;
    const int tx = t & 15, ty = t >> 4;
    const int m0 = blockIdx.x * 64;
    const int ka = t & 7, ma = t >> 3;

    float acc[4][12];
    #pragma unroll
    for (int r = 0; r < 4; r++)
        #pragma unroll
        for (int c = 0; c < 12; c++) acc[r][c] = 0.f;

    for (int k0 = 0; k0 < 584; k0 += 8) {
        As[ka * 68 + ma]      = g_feats[(size_t)(m0 + ma) * FEAT + k0 + ka];
        As[ka * 68 + ma + 32] = g_feats[(size_t)(m0 + ma + 32) * FEAT + k0 + ka];
        #pragma unroll
        for (int i = 0; i < 4; i++) {
            int idx = t + i * 256; int kk = idx >> 7, col = idx & 127;
            Bs[kk * 196 + col] = __ldg(ptw1 + (size_t)(k0 + kk) * 128 + col);
        }
        #pragma unroll
        for (int i = 0; i < 2; i++) {
            int idx = t + i * 256; int kk = idx >> 6, col = idx & 63;
            Bs[kk * 196 + 128 + col] = __ldg(cfw1 + (size_t)(k0 + kk) * 64 + col);
        }
        __syncthreads();
        #pragma unroll
        for (int kk = 0; kk < 8; kk++) {
            float4 a4 = *(const float4*)&As[kk * 68 + ty * 4];
            float4 b0 = *(const float4*)&Bs[kk * 196 + tx * 12];
            float4 b1 = *(const float4*)&Bs[kk * 196 + tx * 12 + 4];
            float4 b2 = *(const float4*)&Bs[kk * 196 + tx * 12 + 8];
            const float av[4]  = {a4.x, a4.y, a4.z, a4.w};
            const float bv[12] = {b0.x, b0.y, b0.z, b0.w,
                                  b1.x, b1.y, b1.z, b1.w,
                                  b2.x, b2.y, b2.z, b2.w};
            #pragma unroll
            for (int r = 0; r < 4; r++)
                #pragma unroll
                for (int c = 0; c < 12; c++)
                    acc[r][c] = fmaf(av[r], bv[c], acc[r][c]);
        }
        __syncthreads();
    }

    #pragma unroll
    for (int c = 0; c < 12; c++) {
        const int j = tx * 12 + c;
        const float bias = (j < 128) ? __ldg(ptb1 + j) : __ldg(cfb1 + j - 128);
        #pragma unroll
        for (int r = 0; r < 4; r++) {
            float v = fmaxf(acc[r][c] + bias, 0.f);
            g_c1[(size_t)(m0 + ty * 4 + r) * 192 + j] = v;
        }
    }
}

// ---------------------------------------------------------------------------
// Kernel 3: second-stage heads. One warp per sample.
// ---------------------------------------------------------------------------
__global__ __launch_bounds__(256) void k_fc2(
    const float* __restrict__ ptw2, const float* __restrict__ ptb2,
    const float* __restrict__ ptw3, const float* __restrict__ ptb3,
    const float* __restrict__ cfw2, const float* __restrict__ cfb2,
    float* __restrict__ out, int nsamp)
{
    const int warp = threadIdx.x >> 5, lane = threadIdx.x & 31;
    const int m = blockIdx.x * 8 + warp;
    if (m >= nsamp) return;
    const float* c1 = g_c1 + (size_t)m * 192;

    float a0 = __ldg(ptb2 + lane), a1 = __ldg(ptb2 + lane + 32);
    #pragma unroll 8
    for (int k4 = 0; k4 < 32; k4++) {
        const float4 h = __ldg((const float4*)(c1 + k4 * 4));
        const int k = k4 * 4;
        a0 = fmaf(h.x, __ldg(ptw2 + (k + 0) * 64 + lane), a0);
        a1 = fmaf(h.x, __ldg(ptw2 + (k + 0) * 64 + lane + 32), a1);
        a0 = fmaf(h.y, __ldg(ptw2 + (k + 1) * 64 + lane), a0);
        a1 = fmaf(h.y, __ldg(ptw2 + (k + 1) * 64 + lane + 32), a1);
        a0 = fmaf(h.z, __ldg(ptw2 + (k + 2) * 64 + lane), a0);
        a1 = fmaf(h.z, __ldg(ptw2 + (k + 2) * 64 + lane + 32), a1);
        a0 = fmaf(h.w, __ldg(ptw2 + (k + 3) * 64 + lane), a0);
        a1 = fmaf(h.w, __ldg(ptw2 + (k + 3) * 64 + lane + 32), a1);
    }
    a0 = fmaxf(a0, 0.f); a1 = fmaxf(a1, 0.f);

    float l0 = a0 * __ldg(ptw3 + lane * 2)     + a1 * __ldg(ptw3 + (lane + 32) * 2);
    float l1 = a0 * __ldg(ptw3 + lane * 2 + 1) + a1 * __ldg(ptw3 + (lane + 32) * 2 + 1);
    const float hc0 = c1[128 + lane], hc1 = c1[160 + lane];
    float cc = hc0 * __ldg(cfw2 + lane) + hc1 * __ldg(cfw2 + lane + 32);

    #pragma unroll
    for (int off = 16; off; off >>= 1) {
        l0 += __shfl_xor_sync(0xffffffffu, l0, off);
        l1 += __shfl_xor_sync(0xffffffffu, l1, off);
        cc += __shfl_xor_sync(0xffffffffu, cc, off);
    }
    if (lane == 0) {
        l0 += __ldg(ptb3 + 0); l1 += __ldg(ptb3 + 1);
        const float mx = fmaxf(l0, l1);
        const float e0 = expf(l0 - mx), e1 = expf(l1 - mx);
        const float inv = 1.f / (e0 + e1);
        const float conf = 1.f / (1.f + expf(-(cc + __ldg(cfb2))));
        out[(size_t)m * 3 + 0] = e0 * inv;
        out[(size_t)m * 3 + 1] = e1 * inv;
        out[(size_t)m * 3 + 2] = conf;
    }
}

// ---------------------------------------------------------------------------
extern "C" void kernel_launch(void* const* d_in, const int* in_sizes, int n_in,
                              void* d_out, int out_size)
{
    const float* board = (const float*)d_in[0];
    // d_in[1] = target_positions (int64) — mathematically unused
    const float* c1w = (const float*)d_in[2];  const float* c1b = (const float*)d_in[3];
    const float* c2w = (const float*)d_in[4];  const float* c2b = (const float*)d_in[5];
    const float* c3w = (const float*)d_in[6];  const float* c3b = (const float*)d_in[7];
    const float* qp  = (const float*)d_in[8];
    const float* ptw1 = (const float*)d_in[9];  const float* ptb1 = (const float*)d_in[10];
    const float* ptw2 = (const float*)d_in[11]; const float* ptb2 = (const float*)d_in[12];
    const float* ptw3 = (const float*)d_in[13]; const float* ptb3 = (const float*)d_in[14];
    const float* cfw1 = (const float*)d_in[15]; const float* cfb1 = (const float*)d_in[16];
    const float* cfw2 = (const float*)d_in[17]; const float* cfb2 = (const float*)d_in[18];

    int B = in_sizes[0] / 108;
    if (B > BATCH_MAX) B = BATCH_MAX;

    k_wt<<<72, 256>>>(c1w, c2w, c3w);
    k_conv<<<(B + 3) / 4, 128>>>(board, c1b, c2b, c3b, qp, B);
    k_fc1<<<B / 64, 256>>>(ptw1, ptb1, cfw1, cfb1);
    k_fc2<<<(B + 7) / 8, 256>>>(ptw2, ptb2, ptw3, ptb3, cfw2, cfb2, (float*)d_out, B);
}

// round 3
// speedup vs baseline: 4.2283x; 1.1212x over previous
#include <cuda_runtime.h>
#include <math.h>

#define BATCH_MAX 65536
#define FEAT 584

typedef unsigned long long u64t;

__device__ float g_feats[(size_t)BATCH_MAX * FEAT];   // conv features + quantum

// Transposed weight copies (lane-coalesced layouts)
__device__ float g_w1t[27 * 16];     // [tap][co]
__device__ float g_w2t[144 * 32];    // [ci*9+tap][co]
__device__ float g_w3t[288 * 64];    // [ci*9+tap][co]

// ---- packed f32x2 helpers -------------------------------------------------
__device__ __forceinline__ float2 ffma2(float2 a, float2 b, float2 c) {
    u64t ua = *(u64t*)&a, ub = *(u64t*)&b, uc = *(u64t*)&c, ud;
    asm("fma.rn.f32x2 %0, %1, %2, %3;" : "=l"(ud) : "l"(ua), "l"(ub), "l"(uc));
    return *(float2*)&ud;
}
__device__ __forceinline__ float2 bcast2(float w) { return make_float2(w, w); }
__device__ __forceinline__ float2 fmax2(float2 a, float2 b) {
    return make_float2(fmaxf(a.x, b.x), fmaxf(a.y, b.y));
}

// ---------------------------------------------------------------------------
// Kernel 0: transpose conv weights into lane-coalesced layouts.
// ---------------------------------------------------------------------------
__global__ void k_wt(const float* __restrict__ w1,
                     const float* __restrict__ w2,
                     const float* __restrict__ w3)
{
    const int i = blockIdx.x * 256 + threadIdx.x;
    if (i < 432)   { int co = i / 27,  r = i - co * 27;  g_w1t[r * 16 + co] = w1[i]; }
    if (i < 4608)  { int co = i / 144, r = i - co * 144; g_w2t[r * 32 + co] = w2[i]; }
    if (i < 18432) { int co = i / 288, r = i - co * 288; g_w3t[r * 64 + co] = w3[i]; }
}

// ---------------------------------------------------------------------------
// conv2 x-half: computes output cols [C0..C0+WOUT) for all 6 rows, 16 input
// channels, fused relu+2x2 maxpool, writes padded pooled 5x5 (f32x2 packed).
// ---------------------------------------------------------------------------
template<int C0, int WIN, int WOUT>
__device__ __forceinline__ void conv2_part(
    const float2* __restrict__ h1p, float2 bias, int lane, float2* __restrict__ pp)
{
    float2 acc[6][WOUT];
    #pragma unroll
    for (int y = 0; y < 6; y++)
        #pragma unroll
        for (int x = 0; x < WOUT; x++) acc[y][x] = bias;

    for (int ci = 0; ci < 16; ci++) {
        float2 w[9];
        #pragma unroll
        for (int i = 0; i < 9; i++) w[i] = bcast2(__ldg(g_w2t + (ci * 9 + i) * 32 + lane));
        const float2* hr = h1p + ci * 64;
        float2 r[3][WIN];
        #pragma unroll
        for (int j = 0; j < WIN; j++) { r[0][j] = hr[C0 + j]; r[1][j] = hr[8 + C0 + j]; }
        #pragma unroll
        for (int y = 0; y < 6; y++) {
            #pragma unroll
            for (int j = 0; j < WIN; j++) r[(y + 2) % 3][j] = hr[(y + 2) * 8 + C0 + j];
            #pragma unroll
            for (int x = 0; x < WOUT; x++) {
                float2 a = acc[y][x];
                a = ffma2(r[(y + 0) % 3][x + 0], w[0], a);
                a = ffma2(r[(y + 0) % 3][x + 1], w[1], a);
                a = ffma2(r[(y + 0) % 3][x + 2], w[2], a);
                a = ffma2(r[(y + 1) % 3][x + 0], w[3], a);
                a = ffma2(r[(y + 1) % 3][x + 1], w[4], a);
                a = ffma2(r[(y + 1) % 3][x + 2], w[5], a);
                a = ffma2(r[(y + 2) % 3][x + 0], w[6], a);
                a = ffma2(r[(y + 2) % 3][x + 1], w[7], a);
                a = ffma2(r[(y + 2) % 3][x + 2], w[8], a);
                acc[y][x] = a;
            }
        }
    }
    // fused relu + 2x2 maxpool -> padded pooled layout
    #pragma unroll
    for (int py = 0; py < 3; py++)
        #pragma unroll
        for (int pxl = 0; pxl < WOUT / 2; pxl++) {
            float2 m = fmax2(fmax2(acc[2 * py][2 * pxl], acc[2 * py][2 * pxl + 1]),
                             fmax2(acc[2 * py + 1][2 * pxl], acc[2 * py + 1][2 * pxl + 1]));
            m = fmax2(m, make_float2(0.f, 0.f));
            const int px = C0 / 2 + pxl;
            pp[lane * 25 + (py + 1) * 5 + (px + 1)] = m;
        }
}

// ---------------------------------------------------------------------------
// Kernel 1: conv pipeline + quantum sim, f32x2 packed, 2 samples per warp.
// 4 warps / block -> 8 samples per block. Dyn smem: 4 * 2016 float2 = 63KB.
// Per-warp float2 regions: inp 192 (3x8x8), h1p 1024 (16x8x8), pp 800 (32x5x5)
// ---------------------------------------------------------------------------
__global__ __launch_bounds__(128) void k_conv(
    const float* __restrict__ board,
    const float* __restrict__ b1,
    const float* __restrict__ b2,
    const float* __restrict__ b3,
    const float* __restrict__ qp, int nsamp)
{
    extern __shared__ float2 smc[];
    const int warp = threadIdx.x >> 5;
    const int lane = threadIdx.x & 31;
    const int pidx = blockIdx.x * 4 + warp;          // sample-pair index
    const int s0 = 2 * pidx;
    if (s0 >= nsamp) return;
    const bool has2 = (s0 + 1 < nsamp);

    float2* inp = smc + (size_t)warp * 2016;
    float2* h1p = inp + 192;
    float2* pp  = inp + 1216;

    const float* bs0 = board + (size_t)s0 * 108;
    const float* bs1 = has2 ? bs0 + 108 : bs0;

    // ---- zero everything (covers all padding)
    #pragma unroll
    for (int i = lane; i < 2016; i += 32) inp[i] = make_float2(0.f, 0.f);
    __syncwarp();

    // ---- load board pair into padded interior
    for (int i = lane; i < 108; i += 32) {
        int ci = i / 36, r = i - ci * 36;
        int y = r / 6, x = r - y * 6;
        inp[ci * 64 + (y + 1) * 8 + (x + 1)] = make_float2(bs0[i], bs1[i]);
    }

    // ---- quantum sim: lanes 0..15 (sample = lane>>3, qubit = lane&7)
    if (lane < 16) {
        const int smp = lane >> 3, qb = lane & 7;
        const int sg = s0 + smp;
        if (sg < nsamp) {
            const float* bq = board + (size_t)sg * 108;
            float xv = bq[qb], xn = bq[(qb + 1) & 7];
            float q = 0.f;
            #pragma unroll
            for (int l = 0; l < 3; l++) {
                float r0 = __ldg(qp + (l * 8 + qb) * 3 + 0);
                float r1 = __ldg(qp + (l * 8 + qb) * 3 + 1);
                float r2 = __ldg(qp + (l * 8 + qb) * 3 + 2);
                q = sinf(r0 * xv) * cosf(r1 * xn) + tanhf(r2 * q);
            }
            g_feats[(size_t)sg * FEAT + 576 + qb] = q;
        }
    }
    __syncwarp();

    // ---- conv1: 3->16, relu.  lane&15 = co, lane>>4 = row-half
    {
        const int co = lane & 15, half = lane >> 4;
        float2 w[27];
        #pragma unroll
        for (int i = 0; i < 27; i++) w[i] = bcast2(__ldg(g_w1t + i * 16 + co));
        const float2 bias = bcast2(__ldg(b1 + co));
        #pragma unroll
        for (int p = 0; p < 18; p++) {
            const int yy = half * 3 + p / 6;
            const int xx = p % 6;
            const int y8 = yy * 8;
            float2 a = bias;
            #pragma unroll
            for (int ci = 0; ci < 3; ci++)
                #pragma unroll
                for (int ky = 0; ky < 3; ky++)
                    #pragma unroll
                    for (int kx = 0; kx < 3; kx++)
                        a = ffma2(inp[ci * 64 + y8 + ky * 8 + xx + kx],
                                  w[ci * 9 + ky * 3 + kx], a);
            h1p[co * 64 + y8 + 8 + xx + 1] = fmax2(a, make_float2(0.f, 0.f));
        }
    }
    __syncwarp();

    // ---- conv2 (+relu+pool fused), lane = co
    {
        const float2 bias2 = bcast2(__ldg(b2 + lane));
        conv2_part<0, 6, 4>(h1p, bias2, lane, pp);
        conv2_part<4, 4, 2>(h1p, bias2, lane, pp);
    }
    __syncwarp();

    // ---- conv3: 32->64, relu.  lane handles co = lane and lane+32
    {
        float2 acc0[9], acc1[9];
        const float2 bz0 = bcast2(__ldg(b3 + lane));
        const float2 bz1 = bcast2(__ldg(b3 + lane + 32));
        #pragma unroll
        for (int i = 0; i < 9; i++) { acc0[i] = bz0; acc1[i] = bz1; }

        for (int ci = 0; ci < 32; ci++) {
            float2 wa[9], wb[9];
            #pragma unroll
            for (int i = 0; i < 9; i++) {
                wa[i] = bcast2(__ldg(g_w3t + (ci * 9 + i) * 64 + lane));
                wb[i] = bcast2(__ldg(g_w3t + (ci * 9 + i) * 64 + lane + 32));
            }
            const float2* ps = pp + ci * 25;
            float2 r[3][5];
            #pragma unroll
            for (int j = 0; j < 5; j++) { r[0][j] = ps[j]; r[1][j] = ps[5 + j]; }
            #pragma unroll
            for (int y = 0; y < 3; y++) {
                #pragma unroll
                for (int j = 0; j < 5; j++) r[(y + 2) % 3][j] = ps[(y + 2) * 5 + j];
                #pragma unroll
                for (int x = 0; x < 3; x++) {
                    float2 a0 = acc0[y * 3 + x], a1 = acc1[y * 3 + x];
                    #pragma unroll
                    for (int ky = 0; ky < 3; ky++)
                        #pragma unroll
                        for (int kx = 0; kx < 3; kx++) {
                            const float2 v = r[(y + ky) % 3][x + kx];
                            a0 = ffma2(v, wa[ky * 3 + kx], a0);
                            a1 = ffma2(v, wb[ky * 3 + kx], a1);
                        }
                    acc0[y * 3 + x] = a0; acc1[y * 3 + x] = a1;
                }
            }
        }
        float* f0 = g_feats + (size_t)s0 * FEAT;
        float* f1 = f0 + FEAT;
        #pragma unroll
        for (int i = 0; i < 9; i++) {
            float2 v0 = fmax2(acc0[i], make_float2(0.f, 0.f));
            float2 v1 = fmax2(acc1[i], make_float2(0.f, 0.f));
            f0[lane * 9 + i] = v0.x;
            f0[(lane + 32) * 9 + i] = v1.x;
            if (has2) { f1[lane * 9 + i] = v0.y; f1[(lane + 32) * 9 + i] = v1.y; }
        }
    }
}

// ---------------------------------------------------------------------------
// Kernel 2 (fused): C1 = relu(feats @ [pt_w1|cf_w1] + b), then both heads.
// GEMM: BM=64, BN=192, BK=8, 256 thr, f32x2 row-pair accumulate.
// Heads: per-warp, weights cached in smem.
// Dyn smem floats: [0,12544) C1s (aliases As/Bs) | [12544) W2s 8192 |
//                  [20736) W3s 128 | [20864) CW2s 64 | [20928) B2s 64  = 20992
// ---------------------------------------------------------------------------
__global__ __launch_bounds__(256) void k_fc1(
    const float* __restrict__ ptw1, const float* __restrict__ ptb1,
    const float* __restrict__ cfw1, const float* __restrict__ cfb1,
    const float* __restrict__ ptw2, const float* __restrict__ ptb2,
    const float* __restrict__ ptw3, const float* __restrict__ ptb3,
    const float* __restrict__ cfw2, const float* __restrict__ cfb2,
    float* __restrict__ out)
{
    extern __shared__ float sfc[];
    float* C1s  = sfc;              // 64 x 196
    float* As   = sfc;              // 8 x 68 (GEMM phase only)
    float* Bs   = sfc + 544;        // 8 x 196
    float* W2s  = sfc + 12544;      // 128 x 64
    float* W3s  = sfc + 20736;      // 64 x 2
    float* CW2s = sfc + 20864;      // 64
    float* B2s  = sfc + 20928;      // 64

    const int t  = threadIdx.x;
    const int tx = t & 15, ty = t >> 4;
    const int m0 = blockIdx.x * 64;
    const int ka = t & 7, ma = t >> 3;

    // preload head weights (consumed after the pre-phase-B syncthreads)
    for (int i = t; i < 8192; i += 256) W2s[i] = __ldg(ptw2 + i);
    if (t < 128) W3s[t] = __ldg(ptw3 + t);
    if (t < 64)  { CW2s[t] = __ldg(cfw2 + t); B2s[t] = __ldg(ptb2 + t); }

    float2 acc2[2][12];
    #pragma unroll
    for (int r = 0; r < 2; r++)
        #pragma unroll
        for (int c = 0; c < 12; c++) acc2[r][c] = make_float2(0.f, 0.f);

    for (int k0 = 0; k0 < 584; k0 += 8) {
        As[ka * 68 + ma]      = g_feats[(size_t)(m0 + ma) * FEAT + k0 + ka];
        As[ka * 68 + ma + 32] = g_feats[(size_t)(m0 + ma + 32) * FEAT + k0 + ka];
        #pragma unroll
        for (int i = 0; i < 4; i++) {
            int idx = t + i * 256; int kk = idx >> 7, col = idx & 127;
            Bs[kk * 196 + col] = __ldg(ptw1 + (size_t)(k0 + kk) * 128 + col);
        }
        #pragma unroll
        for (int i = 0; i < 2; i++) {
            int idx = t + i * 256; int kk = idx >> 6, col = idx & 63;
            Bs[kk * 196 + 128 + col] = __ldg(cfw1 + (size_t)(k0 + kk) * 64 + col);
        }
        __syncthreads();
        #pragma unroll
        for (int kk = 0; kk < 8; kk++) {
            const float2* ap = (const float2*)&As[kk * 68 + ty * 4];
            const float2 a01 = ap[0], a23 = ap[1];
            float4 b0 = *(const float4*)&Bs[kk * 196 + tx * 12];
            float4 b1 = *(const float4*)&Bs[kk * 196 + tx * 12 + 4];
            float4 b2 = *(const float4*)&Bs[kk * 196 + tx * 12 + 8];
            const float bv[12] = {b0.x, b0.y, b0.z, b0.w,
                                  b1.x, b1.y, b1.z, b1.w,
                                  b2.x, b2.y, b2.z, b2.w};
            #pragma unroll
            for (int c = 0; c < 12; c++) {
                const float2 wb = bcast2(bv[c]);
                acc2[0][c] = ffma2(a01, wb, acc2[0][c]);
                acc2[1][c] = ffma2(a23, wb, acc2[1][c]);
            }
        }
        __syncthreads();
    }

    // epilogue: bias + relu -> C1s
    #pragma unroll
    for (int c = 0; c < 12; c++) {
        const int j = tx * 12 + c;
        const float bias = (j < 128) ? __ldg(ptb1 + j) : __ldg(cfb1 + j - 128);
        #pragma unroll
        for (int rp = 0; rp < 2; rp++) {
            C1s[(ty * 4 + 2 * rp)     * 196 + j] = fmaxf(acc2[rp][c].x + bias, 0.f);
            C1s[(ty * 4 + 2 * rp + 1) * 196 + j] = fmaxf(acc2[rp][c].y + bias, 0.f);
        }
    }
    __syncthreads();

    // phase B: heads. warp w -> samples w*8 .. w*8+7
    const int warp = t >> 5, lane = t & 31;
    for (int i = 0; i < 8; i++) {
        const int ml = warp * 8 + i;
        const float* c1 = C1s + ml * 196;
        float a0 = B2s[lane], a1 = B2s[lane + 32];
        #pragma unroll 8
        for (int k = 0; k < 128; k++) {
            const float h = c1[k];
            a0 = fmaf(h, W2s[k * 64 + lane], a0);
            a1 = fmaf(h, W2s[k * 64 + lane + 32], a1);
        }
        a0 = fmaxf(a0, 0.f); a1 = fmaxf(a1, 0.f);

        float l0 = a0 * W3s[lane * 2]     + a1 * W3s[(lane + 32) * 2];
        float l1 = a0 * W3s[lane * 2 + 1] + a1 * W3s[(lane + 32) * 2 + 1];
        float cc = c1[128 + lane] * CW2s[lane] + c1[160 + lane] * CW2s[lane + 32];

        #pragma unroll
        for (int off = 16; off; off >>= 1) {
            l0 += __shfl_xor_sync(0xffffffffu, l0, off);
            l1 += __shfl_xor_sync(0xffffffffu, l1, off);
            cc += __shfl_xor_sync(0xffffffffu, cc, off);
        }
        if (lane == 0) {
            l0 += __ldg(ptb3 + 0); l1 += __ldg(ptb3 + 1);
            const float mx = fmaxf(l0, l1);
            const float e0 = expf(l0 - mx), e1 = expf(l1 - mx);
            const float inv = 1.f / (e0 + e1);
            const float conf = 1.f / (1.f + expf(-(cc + __ldg(cfb2))));
            out[(size_t)(m0 + ml) * 3 + 0] = e0 * inv;
            out[(size_t)(m0 + ml) * 3 + 1] = e1 * inv;
            out[(size_t)(m0 + ml) * 3 + 2] = conf;
        }
    }
}

// ---------------------------------------------------------------------------
extern "C" void kernel_launch(void* const* d_in, const int* in_sizes, int n_in,
                              void* d_out, int out_size)
{
    const float* board = (const float*)d_in[0];
    // d_in[1] = target_positions (int64) — mathematically unused
    const float* c1w = (const float*)d_in[2];  const float* c1b = (const float*)d_in[3];
    const float* c2w = (const float*)d_in[4];  const float* c2b = (const float*)d_in[5];
    const float* c3w = (const float*)d_in[6];  const float* c3b = (const float*)d_in[7];
    const float* qp  = (const float*)d_in[8];
    const float* ptw1 = (const float*)d_in[9];  const float* ptb1 = (const float*)d_in[10];
    const float* ptw2 = (const float*)d_in[11]; const float* ptb2 = (const float*)d_in[12];
    const float* ptw3 = (const float*)d_in[13]; const float* ptb3 = (const float*)d_in[14];
    const float* cfw1 = (const float*)d_in[15]; const float* cfb1 = (const float*)d_in[16];
    const float* cfw2 = (const float*)d_in[17]; const float* cfb2 = (const float*)d_in[18];

    int B = in_sizes[0] / 108;
    if (B > BATCH_MAX) B = BATCH_MAX;

    static bool attr_done = false;
    if (!attr_done) {
        cudaFuncSetAttribute(k_conv, cudaFuncAttributeMaxDynamicSharedMemorySize, 4 * 2016 * 8);
        cudaFuncSetAttribute(k_fc1, cudaFuncAttributeMaxDynamicSharedMemorySize, 20992 * 4);
        attr_done = true;
    }

    const int pairs = (B + 1) / 2;
    k_wt<<<72, 256>>>(c1w, c2w, c3w);
    k_conv<<<(pairs + 3) / 4, 128, 4 * 2016 * 8>>>(board, c1b, c2b, c3b, qp, B);
    k_fc1<<<B / 64, 256, 20992 * 4>>>(ptw1, ptb1, cfw1, cfb1,
                                      ptw2, ptb2, ptw3, ptb3, cfw2, cfb2,
                                      (float*)d_out);
}